// round 4
// baseline (speedup 1.0000x reference)
#include <cuda_runtime.h>
#include <cuda_bf16.h>
#include <cstddef>

// ---------------- problem constants ----------------
#define BATCH 2
#define TSEQ  1024
#define MROWS (BATCH*TSEQ)      // 2048
#define DMODEL 768
#define NHEAD 12
#define DHEAD 64
#define DMLP  3072
#define NLAYER 12
#define VOCAB 50257

// ---------------- scratch (static device globals; no allocation) ----------------
__device__ float g_x [MROWS*DMODEL];   // residual stream
__device__ float g_h [MROWS*DMODEL];   // LN output
__device__ float g_q [MROWS*DMODEL];
__device__ float g_k [MROWS*DMODEL];
__device__ float g_v [MROWS*DMODEL];
__device__ float g_z [MROWS*DMODEL];   // attention output (pre-proj)
__device__ float g_m [MROWS*DMLP];     // MLP hidden

// ---------------- helpers ----------------
__device__ __forceinline__ float gelu_f(float x){
    // exact GELU: 0.5*x*(1+erf(x/sqrt(2))) — matches jax.nn.gelu(approximate=False)
    return 0.5f * x * (1.0f + erff(x * 0.70710678118654752440f));
}

// ---------------- embedding: x = emb[ids] + pos ----------------
__global__ void embed_k(const int* __restrict__ ids,
                        const float* __restrict__ emb,
                        const float* __restrict__ pos,
                        float* __restrict__ x)
{
    int row = blockIdx.x;                 // b*T + t
    int t   = row % TSEQ;
    int id  = ids[row];
    const float* er = emb + (size_t)id * DMODEL;
    const float* pr = pos + (size_t)t  * DMODEL;
    float* xr = x + (size_t)row * DMODEL;
    int tid = threadIdx.x;                // 256 threads, 3 elems each
    xr[tid]       = er[tid]       + pr[tid];
    xr[tid + 256] = er[tid + 256] + pr[tid + 256];
    xr[tid + 512] = er[tid + 512] + pr[tid + 512];
}

// ---------------- layernorm: one block (256 thr) per row, D=768 ----------------
__global__ void ln_k(const float* __restrict__ x,
                     const float* __restrict__ g,
                     const float* __restrict__ b,
                     float* __restrict__ out)
{
    __shared__ float red0[8], red1[8];
    int row = blockIdx.x, tid = threadIdx.x;
    const float* xr = x + (size_t)row * DMODEL;
    float v0 = xr[tid], v1 = xr[tid + 256], v2 = xr[tid + 512];
    float s  = v0 + v1 + v2;
    float s2 = v0*v0 + v1*v1 + v2*v2;
    #pragma unroll
    for (int off = 16; off; off >>= 1){
        s  += __shfl_xor_sync(0xffffffffu, s,  off);
        s2 += __shfl_xor_sync(0xffffffffu, s2, off);
    }
    int w = tid >> 5;
    if ((tid & 31) == 0){ red0[w] = s; red1[w] = s2; }
    __syncthreads();
    if (tid < 32){
        s  = (tid < 8) ? red0[tid] : 0.f;
        s2 = (tid < 8) ? red1[tid] : 0.f;
        #pragma unroll
        for (int off = 4; off; off >>= 1){
            s  += __shfl_xor_sync(0xffffffffu, s,  off);
            s2 += __shfl_xor_sync(0xffffffffu, s2, off);
        }
        if (tid == 0){ red0[0] = s; red1[0] = s2; }
    }
    __syncthreads();
    float mean = red0[0] * (1.f/768.f);
    float var  = red1[0] * (1.f/768.f) - mean * mean;
    float r    = rsqrtf(var + 1e-5f);
    float* orow = out + (size_t)row * DMODEL;
    orow[tid]       = (v0 - mean) * r * g[tid]       + b[tid];
    orow[tid + 256] = (v1 - mean) * r * g[tid + 256] + b[tid + 256];
    orow[tid + 512] = (v2 - mean) * r * g[tid + 512] + b[tid + 512];
}

// ---------------- tiled fp32 GEMM:  C = epi(A[M,K] * B[K,N] + bias) ----------------
// EPI: 0 = none, 1 = GELU, 2 = add residual (res[M,N])
template<int BM, int BN, int BK, int TM, int TN, int EPI>
__global__ void gemm_k(const float* __restrict__ A, const float* __restrict__ B,
                       const float* __restrict__ bias, const float* res,
                       float* C, int M, int N, int K)
{
    __shared__ float As[BK][BM];
    __shared__ float Bs[BK][BN];
    constexpr int NT = 256;
    const int tid = threadIdx.x;
    const int tx  = tid % (BN / TN);
    const int ty  = tid / (BN / TN);
    const int m0  = blockIdx.y * BM;
    const int n0  = blockIdx.x * BN;

    float acc[TM][TN];
    #pragma unroll
    for (int i = 0; i < TM; i++)
        #pragma unroll
        for (int j = 0; j < TN; j++) acc[i][j] = 0.f;

    const bool nvec = ((N & 3) == 0);

    for (int k0 = 0; k0 < K; k0 += BK){
        // load A tile (transposed into As[k][m]); M, K multiples of tile dims
        #pragma unroll
        for (int it = 0; it < (BM * BK) / (NT * 4); ++it){
            int e = (it * NT + tid) * 4;
            int r = e / BK, c = e % BK;
            float4 a4 = *(const float4*)(A + (size_t)(m0 + r) * K + k0 + c);
            As[c + 0][r] = a4.x; As[c + 1][r] = a4.y;
            As[c + 2][r] = a4.z; As[c + 3][r] = a4.w;
        }
        // load B tile (N may be ragged / unaligned, e.g. vocab=50257)
        #pragma unroll
        for (int it = 0; it < (BK * BN) / (NT * 4); ++it){
            int e = (it * NT + tid) * 4;
            int r = e / BN, c = e % BN;
            int gn = n0 + c;
            float4 b4;
            if (nvec && gn + 3 < N){
                b4 = *(const float4*)(B + (size_t)(k0 + r) * N + gn);
            } else {
                const float* bp = B + (size_t)(k0 + r) * N;
                b4.x = (gn + 0 < N) ? bp[gn + 0] : 0.f;
                b4.y = (gn + 1 < N) ? bp[gn + 1] : 0.f;
                b4.z = (gn + 2 < N) ? bp[gn + 2] : 0.f;
                b4.w = (gn + 3 < N) ? bp[gn + 3] : 0.f;
            }
            *(float4*)&Bs[r][c] = b4;
        }
        __syncthreads();
        #pragma unroll
        for (int kk = 0; kk < BK; ++kk){
            float ra[TM], rb[TN];
            #pragma unroll
            for (int i = 0; i < TM; i += 4)
                *(float4*)&ra[i] = *(const float4*)&As[kk][ty * TM + i];
            #pragma unroll
            for (int j = 0; j < TN; j += 4)
                *(float4*)&rb[j] = *(const float4*)&Bs[kk][tx * TN + j];
            #pragma unroll
            for (int i = 0; i < TM; i++)
                #pragma unroll
                for (int j = 0; j < TN; j++)
                    acc[i][j] = fmaf(ra[i], rb[j], acc[i][j]);
        }
        __syncthreads();
    }

    #pragma unroll
    for (int i = 0; i < TM; i++){
        int m = m0 + ty * TM + i;
        #pragma unroll
        for (int j = 0; j < TN; j++){
            int n = n0 + tx * TN + j;
            if (n < N){
                float v = acc[i][j] + bias[n];
                if (EPI == 1) v = gelu_f(v);
                if (EPI == 2) v += res[(size_t)m * N + n];
                C[(size_t)m * N + n] = v;
            }
        }
    }
}

// ---------------- fused causal attention (flash-style, fp32) ----------------
// One block per (b*h, 64-row q tile). 256 threads as 16x16.
// smem: Qt (Q^T), Kt (K^T, later aliased as P[q][k]), Vs -> exactly 48 KB.
__global__ void attn_k(const float* __restrict__ Qg, const float* __restrict__ Kg,
                       const float* __restrict__ Vg, float* __restrict__ Og)
{
    __shared__ float Qt[64][64];   // Qt[d][q]
    __shared__ float Kt[64][64];   // Kt[d][k]; reused as P[q][k]
    __shared__ float Vs[64][64];   // Vs[k][d]

    const int tid = threadIdx.x;
    const int tx  = tid & 15, ty = tid >> 4;
    const int bh  = blockIdx.y;
    const int b   = bh / NHEAD, h = bh % NHEAD;
    const int q0  = blockIdx.x * 64;
    const size_t base = (size_t)b * TSEQ * DMODEL + (size_t)h * DHEAD;

    // load Q tile transposed
    #pragma unroll
    for (int it = 0; it < 4; ++it){
        int e = (it * 256 + tid) * 4;
        int r = e >> 6, c = e & 63;
        float4 q4 = *(const float4*)(Qg + base + (size_t)(q0 + r) * DMODEL + c);
        Qt[c + 0][r] = q4.x; Qt[c + 1][r] = q4.y;
        Qt[c + 2][r] = q4.z; Qt[c + 3][r] = q4.w;
    }

    float m_i[4], l_i[4], o[4][4];
    #pragma unroll
    for (int i = 0; i < 4; i++){
        m_i[i] = -1e30f; l_i[i] = 0.f;
        #pragma unroll
        for (int j = 0; j < 4; j++) o[i][j] = 0.f;
    }

    const int nkt = blockIdx.x + 1;          // causal: only tiles with k0 <= q0
    for (int kt = 0; kt < nkt; ++kt){
        const int k0 = kt * 64;
        __syncthreads();                     // protect Kt/Vs (and Qt on first iter)
        #pragma unroll
        for (int it = 0; it < 4; ++it){
            int e = (it * 256 + tid) * 4;
            int r = e >> 6, c = e & 63;
            float4 k4 = *(const float4*)(Kg + base + (size_t)(k0 + r) * DMODEL + c);
            Kt[c + 0][r] = k4.x; Kt[c + 1][r] = k4.y;
            Kt[c + 2][r] = k4.z; Kt[c + 3][r] = k4.w;
            *(float4*)&Vs[r][c] = *(const float4*)(Vg + base + (size_t)(k0 + r) * DMODEL + c);
        }
        __syncthreads();

        // S = Q K^T
        float s[4][4];
        #pragma unroll
        for (int i = 0; i < 4; i++)
            #pragma unroll
            for (int j = 0; j < 4; j++) s[i][j] = 0.f;
        #pragma unroll 16
        for (int d = 0; d < 64; ++d){
            float qa[4], kb[4];
            *(float4*)qa = *(const float4*)&Qt[d][ty * 4];
            *(float4*)kb = *(const float4*)&Kt[d][tx * 4];
            #pragma unroll
            for (int i = 0; i < 4; i++)
                #pragma unroll
                for (int j = 0; j < 4; j++)
                    s[i][j] = fmaf(qa[i], kb[j], s[i][j]);
        }

        // scale + causal mask
        #pragma unroll
        for (int i = 0; i < 4; i++){
            int qg = q0 + ty * 4 + i;
            #pragma unroll
            for (int j = 0; j < 4; j++){
                int kg = k0 + tx * 4 + j;
                s[i][j] = (kg <= qg) ? s[i][j] * 0.125f : -1e30f;
            }
        }

        // online softmax (row reductions over the 16 tx lanes)
        float corr[4];
        #pragma unroll
        for (int i = 0; i < 4; i++){
            float mloc = fmaxf(fmaxf(s[i][0], s[i][1]), fmaxf(s[i][2], s[i][3]));
            #pragma unroll
            for (int off = 8; off; off >>= 1)
                mloc = fmaxf(mloc, __shfl_xor_sync(0xffffffffu, mloc, off, 16));
            float mn = fmaxf(m_i[i], mloc);
            corr[i] = expf(m_i[i] - mn);
            m_i[i]  = mn;
            float rs = 0.f;
            #pragma unroll
            for (int j = 0; j < 4; j++){
                float p = expf(s[i][j] - mn);   // masked -> exp(-huge) = 0
                s[i][j] = p;
                rs += p;
            }
            #pragma unroll
            for (int off = 8; off; off >>= 1)
                rs += __shfl_xor_sync(0xffffffffu, rs, off, 16);
            l_i[i] = l_i[i] * corr[i] + rs;
            #pragma unroll
            for (int j = 0; j < 4; j++) o[i][j] *= corr[i];
        }

        __syncthreads();                     // everyone done reading Kt as K^T
        #pragma unroll
        for (int i = 0; i < 4; i++)
            #pragma unroll
            for (int j = 0; j < 4; j++)
                Kt[ty * 4 + i][tx * 4 + j] = s[i][j];   // P[q][k]
        __syncthreads();

        // O += P V
        #pragma unroll 16
        for (int k = 0; k < 64; ++k){
            float vb[4];
            *(float4*)vb = *(const float4*)&Vs[k][tx * 4];
            #pragma unroll
            for (int i = 0; i < 4; i++){
                float p = Kt[ty * 4 + i][k];
                #pragma unroll
                for (int j = 0; j < 4; j++)
                    o[i][j] = fmaf(p, vb[j], o[i][j]);
            }
        }
    }

    // normalize + store
    #pragma unroll
    for (int i = 0; i < 4; i++){
        float inv = 1.f / l_i[i];
        int qg = q0 + ty * 4 + i;
        float4 r4 = make_float4(o[i][0]*inv, o[i][1]*inv, o[i][2]*inv, o[i][3]*inv);
        *(float4*)(Og + base + (size_t)qg * DMODEL + tx * 4) = r4;
    }
}

// ---------------- host orchestration ----------------
extern "C" void kernel_launch(void* const* d_in, const int* in_sizes, int n_in,
                              void* d_out, int out_size)
{
    const int*   ids = (const int*)  d_in[0];
    const float* emb = (const float*)d_in[1];
    const float* pos = (const float*)d_in[2];
    const float* Wq  = (const float*)d_in[3],  *bq = (const float*)d_in[4];
    const float* Wk  = (const float*)d_in[5],  *bk = (const float*)d_in[6];
    const float* Wv  = (const float*)d_in[7],  *bv = (const float*)d_in[8];
    const float* Wo  = (const float*)d_in[9],  *bo = (const float*)d_in[10];
    const float* l1g = (const float*)d_in[11], *l1b = (const float*)d_in[12];
    const float* l2g = (const float*)d_in[13], *l2b = (const float*)d_in[14];
    const float* W1  = (const float*)d_in[15], *b1 = (const float*)d_in[16];
    const float* W2  = (const float*)d_in[17], *b2 = (const float*)d_in[18];
    const float* lfg = (const float*)d_in[19], *lfb = (const float*)d_in[20];
    const float* Wu  = (const float*)d_in[21], *bu = (const float*)d_in[22];
    float* out = (float*)d_out;

    float *x, *h, *q, *k, *v, *z, *mm;
    cudaGetSymbolAddress((void**)&x,  g_x);
    cudaGetSymbolAddress((void**)&h,  g_h);
    cudaGetSymbolAddress((void**)&q,  g_q);
    cudaGetSymbolAddress((void**)&k,  g_k);
    cudaGetSymbolAddress((void**)&v,  g_v);
    cudaGetSymbolAddress((void**)&z,  g_z);
    cudaGetSymbolAddress((void**)&mm, g_m);

    const int M = MROWS, D = DMODEL, DM = DMLP, Vn = VOCAB;
    dim3 g64(D / 64, M / 64);                       // (12, 32)

    embed_k<<<M, 256>>>(ids, emb, pos, x);

    for (int l = 0; l < NLAYER; ++l){
        const size_t oD2 = (size_t)l * D * D;
        ln_k<<<M, 256>>>(x, l1g + l * D, l1b + l * D, h);
        gemm_k<64,64,16,4,4,0><<<g64, 256>>>(h, Wq + oD2, bq + l * D, nullptr, q, M, D, D);
        gemm_k<64,64,16,4,4,0><<<g64, 256>>>(h, Wk + oD2, bk + l * D, nullptr, k, M, D, D);
        gemm_k<64,64,16,4,4,0><<<g64, 256>>>(h, Wv + oD2, bv + l * D, nullptr, v, M, D, D);
        attn_k<<<dim3(TSEQ / 64, BATCH * NHEAD), 256>>>(q, k, v, z);
        gemm_k<64,64,16,4,4,2><<<g64, 256>>>(z, Wo + oD2, bo + l * D, x, x, M, D, D);
        ln_k<<<M, 256>>>(x, l2g + l * D, l2b + l * D, h);
        gemm_k<128,128,16,8,8,1><<<dim3(DM / 128, M / 128), 256>>>(
            h, W1 + (size_t)l * D * DM, b1 + l * DM, nullptr, mm, M, DM, D);
        gemm_k<64,64,16,4,4,2><<<g64, 256>>>(mm, W2 + (size_t)l * DM * D, b2 + l * D, x, x, M, D, DM);
    }

    ln_k<<<M, 256>>>(x, lfg, lfb, h);
    gemm_k<128,128,16,8,8,0><<<dim3((Vn + 127) / 128, M / 128), 256>>>(
        h, Wu, bu, nullptr, out, M, Vn, D);
}